// round 2
// baseline (speedup 1.0000x reference)
#include <cuda_runtime.h>
#include <cstdint>

// ---------------------------------------------------------------------------
// MPS_33930241638883: 20-qubit statevector, K=1, fully fused single kernel.
//  - 15 two-local gates on (q,q+1) compose to ONE 4x4 unitary U, identical
//    for all q (theta index is i, not q*15+i).
//  - support after gate q is 2^(q+2): gates 0..10 evolve a 4096-amp head
//    state (m-space, m = n>>8); gates 11..18 touch only the low 9 index bits
//    -> per 512-group output = M[512x2] @ (a,b) with fixed M.
//  - EVERY block redundantly builds U (parallel elements + tree matmul),
//    then warps 0-3 build S1 while warps 4-7 build M (independent),
//    then the block writes its 4 groups (2048 outputs) with float4 stores.
// ---------------------------------------------------------------------------

__device__ __forceinline__ float2 cmul(float2 a, float2 b) {
    return make_float2(a.x * b.x - a.y * b.y, a.x * b.y + a.y * b.x);
}
__device__ __forceinline__ float2 cadd(float2 a, float2 b) {
    return make_float2(a.x + b.x, a.y + b.y);
}

// basis-change 2x2: p=1 X->RY(-pi/2), p=2 Y->RX(+pi/2), p=3 Z->I
__device__ __forceinline__ float2 basisB(int p, int i, int j) {
    const float C = 0.70710678118654752f;
    if (p == 1) {                       // [[C, C], [-C, C]]
        return make_float2((i == 1 && j == 0) ? -C : C, 0.f);
    } else if (p == 2) {                // [[C,-iC],[-iC,C]]
        return (i == j) ? make_float2(C, 0.f) : make_float2(0.f, -C);
    } else {
        return (i == j) ? make_float2(1.f, 0.f) : make_float2(0.f, 0.f);
    }
}

// rotation 2x2: p=1 RX, p=2 RY, p=3 RZ
__device__ __forceinline__ float2 rotR(int p, int i, int j, float ch, float sh) {
    if (p == 1) {                       // [[c,-is],[-is,c]]
        return (i == j) ? make_float2(ch, 0.f) : make_float2(0.f, -sh);
    } else if (p == 2) {                // [[c,-s],[s,c]]
        if (i == j) return make_float2(ch, 0.f);
        return (i == 0) ? make_float2(-sh, 0.f) : make_float2(sh, 0.f);
    } else {                            // diag(e^-it/2, e^it/2)
        if (i != j) return make_float2(0.f, 0.f);
        return (j == 0) ? make_float2(ch, -sh) : make_float2(ch, sh);
    }
}

// element (r,c) of gate i's 4x4 matrix, fully local (no smem)
__device__ __forceinline__ float2 gateElem(int i, int r, int c, float ch, float sh) {
    // pauli codes: i<3 -> (I, i+1); else p0 = (i-3)/4+1, p1 = (i-3)%4
    int p0, p1;
    if (i < 3) { p0 = 0; p1 = i + 1; }
    else       { p0 = ((i - 3) >> 2) + 1; p1 = (i - 3) & 3; }
    const int ar = r >> 1, br = r & 1, ac = c >> 1, bc = c & 1;

    if (p0 == 0)                        // rotation on low wire only
        return (ar == ac) ? rotR(p1, br, bc, ch, sh) : make_float2(0.f, 0.f);
    if (p1 == 0)                        // rotation on high wire only
        return (br == bc) ? rotR(p0, ar, ac, ch, sh) : make_float2(0.f, 0.f);

    // G = pre * D * pre,  D_k = e^{-it/2} for k in {0,3}, e^{+it/2} otherwise
    float2 acc = make_float2(0.f, 0.f);
    #pragma unroll
    for (int k = 0; k < 4; k++) {
        const int ak = k >> 1, bk = k & 1;
        float2 Prk = cmul(basisB(p0, ar, ak), basisB(p1, br, bk));
        float2 Pkc = cmul(basisB(p0, ak, ac), basisB(p1, bk, bc));
        float2 Dk = (k == 0 || k == 3) ? make_float2(ch, -sh) : make_float2(ch, sh);
        acc = cadd(acc, cmul(cmul(Prk, Dk), Pkc));
    }
    return acc;
}

__device__ __forceinline__ void mat4vec(const float2* u,
                                        float2& v0, float2& v1,
                                        float2& v2, float2& v3) {
    float2 a0 = cadd(cadd(cmul(u[0],  v0), cmul(u[1],  v1)),
                     cadd(cmul(u[2],  v2), cmul(u[3],  v3)));
    float2 a1 = cadd(cadd(cmul(u[4],  v0), cmul(u[5],  v1)),
                     cadd(cmul(u[6],  v2), cmul(u[7],  v3)));
    float2 a2 = cadd(cadd(cmul(u[8],  v0), cmul(u[9],  v1)),
                     cadd(cmul(u[10], v2), cmul(u[11], v3)));
    float2 a3 = cadd(cadd(cmul(u[12], v0), cmul(u[13], v1)),
                     cadd(cmul(u[14], v2), cmul(u[15], v3)));
    v0 = a0; v1 = a1; v2 = a2; v3 = a3;
}

__device__ __forceinline__ float probOf(float4 m, float4 ab) {
    // |m0*a + m1*b|^2 with m = (m0.re, m0.im, m1.re, m1.im), ab = (a.re,a.im,b.re,b.im)
    float cr = m.x * ab.x - m.y * ab.y + m.z * ab.z - m.w * ab.w;
    float ci = m.x * ab.y + m.y * ab.x + m.z * ab.w + m.w * ab.z;
    return cr * cr + ci * ci;
}

__global__ void __launch_bounds__(256, 4) fused_kernel(const float* __restrict__ params,
                                                       float* __restrict__ out) {
    __shared__ float2 s1[4096];       // head state (m-space), 32KB
    __shared__ float2 vm[1024];       // M columns [j*2+col], 8KB
    __shared__ float2 bufA[256];      // 16 matrices x 16 elems, ping
    __shared__ float2 bufB[256];      // pong

    const int tid = threadIdx.x;

    // ---- init states (overlap with gate-matrix construction) ----
    for (int i = tid; i < 4096; i += 256)
        s1[i] = make_float2(0.f, 0.f);
    for (int i = tid; i < 1024; i += 256)
        vm[i] = make_float2(0.f, 0.f);

    // ---- build all 15 gate matrices in parallel: thread -> (mat, elem) ----
    {
        const int m = tid >> 4;          // 0..15
        const int e = tid & 15;
        const int r = e >> 2, c = e & 3;
        float2 g;
        if (m < 15) {
            float th = __ldg(&params[m]);
            float ch = cosf(0.5f * th);
            float sh = sinf(0.5f * th);
            g = gateElem(m, r, c, ch, sh);
        } else {                         // pad with identity
            g = (r == c) ? make_float2(1.f, 0.f) : make_float2(0.f, 0.f);
        }
        bufA[tid] = g;
    }
    __syncthreads();

    if (tid == 0) {
        s1[0] = make_float2(1.f, 0.f);
        vm[0 * 2 + 0]   = make_float2(1.f, 0.f);   // column 0: j=0
        vm[256 * 2 + 1] = make_float2(1.f, 0.f);   // column 1: j=256
    }

    // ---- tree-reduce 16 matrices -> U = G14 * ... * G0 (4 steps) ----
    {
        float2* src = bufA;
        float2* dst = bufB;
        for (int cnt = 8; cnt >= 1; cnt >>= 1) {
            const int m = tid >> 4;
            if (m < cnt) {
                const int r = (tid >> 2) & 3, c = tid & 3;
                float2 acc = make_float2(0.f, 0.f);
                #pragma unroll
                for (int k = 0; k < 4; k++)
                    acc = cadd(acc, cmul(src[(2 * m + 1) * 16 + r * 4 + k],
                                         src[(2 * m) * 16 + k * 4 + c]));
                dst[m * 16 + (tid & 15)] = acc;
            }
            __syncthreads();
            float2* t = src; src = dst; dst = t;
        }
        // U now in src[0..15] (src == bufA after 4 swaps)
    }

    float2 u[16];
    #pragma unroll
    for (int k = 0; k < 16; k++) u[k] = bufA[k];

    // ---- concurrent: warps 0-3 evolve head (gates 0..10),
    //                  warps 4-7 build M (gates 11..18) ----
    if (tid < 128) {
        for (int q = 0; q <= 10; q++) {
            const int nb = 1 << q;              // sparsity: only supported quads
            const int s  = 1 << (10 - q);
            for (int t = tid; t < nb; t += 128) {
                const int b = t << (12 - q);
                float2 v0 = s1[b], v1 = s1[b + s],
                       v2 = s1[b + 2 * s], v3 = s1[b + 3 * s];
                mat4vec(u, v0, v1, v2, v3);
                s1[b] = v0; s1[b + s] = v1;
                s1[b + 2 * s] = v2; s1[b + 3 * s] = v3;
            }
            asm volatile("bar.sync 1, 128;" ::: "memory");
        }
    } else {
        const int lt = tid - 128;               // 0..127, one quad each
        for (int q = 11; q <= 18; q++) {
            const int lg = 18 - q;
            const int s  = 1 << lg;
            const int b  = (lt & (s - 1)) | ((lt >> lg) << (lg + 2));
            #pragma unroll
            for (int col = 0; col < 2; col++) {
                float2 v0 = vm[(b)         * 2 + col];
                float2 v1 = vm[(b + s)     * 2 + col];
                float2 v2 = vm[(b + 2 * s) * 2 + col];
                float2 v3 = vm[(b + 3 * s) * 2 + col];
                mat4vec(u, v0, v1, v2, v3);
                vm[(b)         * 2 + col] = v0;
                vm[(b + s)     * 2 + col] = v1;
                vm[(b + 2 * s) * 2 + col] = v2;
                vm[(b + 3 * s) * 2 + col] = v3;
            }
            asm volatile("bar.sync 2, 128;" ::: "memory");
        }
    }
    __syncthreads();

    // ---- epilogue: this block writes 4 groups (2048 outputs) ----
    // float4 view of vm IS M[j] = (m0.re,m0.im,m1.re,m1.im);
    // float4 view of s1 IS (a,b) per group.
    const float4* m4  = (const float4*)vm;
    const float4* s14 = (const float4*)s1;
    float4* out4 = (float4*)out;

    const int lt   = tid & 127;
    const int half = tid >> 7;

    float4 m0 = m4[lt * 4 + 0];
    float4 m1 = m4[lt * 4 + 1];
    float4 m2 = m4[lt * 4 + 2];
    float4 m3 = m4[lt * 4 + 3];

    const int gbase = blockIdx.x * 4;
    #pragma unroll
    for (int it = 0; it < 2; it++) {
        const int g = gbase + it * 2 + half;
        const float4 ab = s14[g];
        float4 r;
        r.x = probOf(m0, ab);
        r.y = probOf(m1, ab);
        r.z = probOf(m2, ab);
        r.w = probOf(m3, ab);
        out4[g * 128 + lt] = r;
    }
}

extern "C" void kernel_launch(void* const* d_in, const int* in_sizes, int n_in,
                              void* d_out, int out_size) {
    const float* params = (const float*)d_in[0];
    float* out = (float*)d_out;
    fused_kernel<<<512, 256>>>(params, out);
}

// round 4
// speedup vs baseline: 4.2239x; 4.2239x over previous
#include <cuda_runtime.h>
#include <cstdint>

// ---------------------------------------------------------------------------
// MPS_33930241638883: 20-qubit staircase circuit, K=1.
// Bond-dimension-2 MPS closed form:
//   psi(x0..x19) = e_{x19}^T . T[x18] ... T[x1] . v(x0)
// with T[x]_{t,s} = U[2x+t, 2s], v(x0)_s = U[2x0+s, 0], and x_w = bit (19-w)
// of the output index n. U = composed 4x4 two-local block (same for all q).
// n = g*512 + j: g = x0..x10 (bits 19..9), j = x11..x19 (bits 8..0).
//
// Each of 512 blocks redundantly builds U (parallel gate elements + 4-step
// tree matmul), tables T and Y[a,b]=T[a].T[b], its 4 head vectors ab(g)
// (10 chained 2x2 matvecs), then each thread computes 2 tail row-vectors
// m(j) (4 row-matvecs) and writes 8 outputs |m(j).ab(g)|^2, coalesced.
//
// NB (round-3 bug): in j, the LOWER bit of each 2-bit field is the LEFT
// matrix of the pair product, so Y indices must be bit-reversed 2-bit fields.
// ---------------------------------------------------------------------------

__device__ __forceinline__ float2 cmul(float2 a, float2 b) {
    return make_float2(a.x * b.x - a.y * b.y, a.x * b.y + a.y * b.x);
}
__device__ __forceinline__ float2 cadd(float2 a, float2 b) {
    return make_float2(a.x + b.x, a.y + b.y);
}
__device__ __forceinline__ float2 cfma2(float2 a, float2 b, float2 acc) {
    acc.x = fmaf(a.x, b.x, fmaf(-a.y, b.y, acc.x));
    acc.y = fmaf(a.x, b.y, fmaf(a.y, b.x, acc.y));
    return acc;
}

// basis-change 2x2: p=1 X->RY(-pi/2), p=2 Y->RX(+pi/2), p=3 Z->I
__device__ __forceinline__ float2 basisB(int p, int i, int j) {
    const float C = 0.70710678118654752f;
    if (p == 1) {                       // [[C, C], [-C, C]]
        return make_float2((i == 1 && j == 0) ? -C : C, 0.f);
    } else if (p == 2) {                // [[C,-iC],[-iC,C]]
        return (i == j) ? make_float2(C, 0.f) : make_float2(0.f, -C);
    } else {
        return (i == j) ? make_float2(1.f, 0.f) : make_float2(0.f, 0.f);
    }
}

// rotation 2x2: p=1 RX, p=2 RY, p=3 RZ
__device__ __forceinline__ float2 rotR(int p, int i, int j, float ch, float sh) {
    if (p == 1) {
        return (i == j) ? make_float2(ch, 0.f) : make_float2(0.f, -sh);
    } else if (p == 2) {
        if (i == j) return make_float2(ch, 0.f);
        return (i == 0) ? make_float2(-sh, 0.f) : make_float2(sh, 0.f);
    } else {
        if (i != j) return make_float2(0.f, 0.f);
        return (j == 0) ? make_float2(ch, -sh) : make_float2(ch, sh);
    }
}

// element (r,c) of gate i's 4x4 matrix (verified in rounds 1/2)
__device__ __forceinline__ float2 gateElem(int i, int r, int c, float ch, float sh) {
    int p0, p1;
    if (i < 3) { p0 = 0; p1 = i + 1; }
    else       { p0 = ((i - 3) >> 2) + 1; p1 = (i - 3) & 3; }
    const int ar = r >> 1, br = r & 1, ac = c >> 1, bc = c & 1;

    if (p0 == 0)
        return (ar == ac) ? rotR(p1, br, bc, ch, sh) : make_float2(0.f, 0.f);
    if (p1 == 0)
        return (br == bc) ? rotR(p0, ar, ac, ch, sh) : make_float2(0.f, 0.f);

    float2 acc = make_float2(0.f, 0.f);
    #pragma unroll
    for (int k = 0; k < 4; k++) {
        const int ak = k >> 1, bk = k & 1;
        float2 Prk = cmul(basisB(p0, ar, ak), basisB(p1, br, bk));
        float2 Pkc = cmul(basisB(p0, ak, ac), basisB(p1, bk, bc));
        float2 Dk = (k == 0 || k == 3) ? make_float2(ch, -sh) : make_float2(ch, sh);
        acc = cadd(acc, cmul(cmul(Prk, Dk), Pkc));
    }
    return acc;
}

__global__ void __launch_bounds__(256, 8) mps_kernel(const float* __restrict__ params,
                                                     float* __restrict__ out) {
    __shared__ float2 bufA[256];     // 16 gate matrices -> U
    __shared__ float2 bufB[256];
    __shared__ float2 sT[8];         // T[b] at b*4 + t*2 + s   (row t, col s)
    __shared__ float2 sY[16];        // Y[a,b]=T[a].T[b] at (a*2+b)*4 + r*2 + c
    __shared__ float2 sAB[8];        // ab[g][s], g = 0..3 local

    const int tid = threadIdx.x;

    // ---- build 15 gate matrices in parallel (16th pads to identity) ----
    {
        const int m = tid >> 4;          // 0..15
        const int e = tid & 15;
        const int r = e >> 2, c = e & 3;
        float2 g;
        if (m < 15) {
            float th = __ldg(&params[m]);
            float ch = cosf(0.5f * th);
            float sh = sinf(0.5f * th);
            g = gateElem(m, r, c, ch, sh);
        } else {
            g = (r == c) ? make_float2(1.f, 0.f) : make_float2(0.f, 0.f);
        }
        bufA[tid] = g;
    }
    __syncthreads();

    // ---- tree-reduce: U = G15 * ... * G0 (4 rounds) ----
    {
        float2* src = bufA;
        float2* dst = bufB;
        for (int cnt = 8; cnt >= 1; cnt >>= 1) {
            const int m = tid >> 4;
            if (m < cnt) {
                const int r = (tid >> 2) & 3, c = tid & 3;
                float2 acc = make_float2(0.f, 0.f);
                #pragma unroll
                for (int k = 0; k < 4; k++)
                    acc = cfma2(src[(2 * m + 1) * 16 + r * 4 + k],
                                src[(2 * m) * 16 + k * 4 + c], acc);
                dst[m * 16 + (tid & 15)] = acc;
            }
            __syncthreads();
            float2* t = src; src = dst; dst = t;
        }
        // U in bufA[0..15], element (row,col) at bufA[row*4+col]
    }

    // ---- extract transfer matrices: T[b]_{t,s} = U[2b+t, 2s] ----
    if (tid < 8) {
        const int b = tid >> 2, t = (tid >> 1) & 1, s = tid & 1;
        sT[tid] = bufA[(2 * b + t) * 4 + 2 * s];
    }
    __syncthreads();

    // ---- pair table Y[a,b] = T[a] . T[b]  (threads 0..15) ----
    if (tid < 16) {
        const int a = tid >> 3, b = (tid >> 2) & 1;
        const int r = (tid >> 1) & 1, c = tid & 1;
        float2 acc = cmul(sT[a * 4 + r * 2 + 0], sT[b * 4 + 0 * 2 + c]);
        acc = cfma2(sT[a * 4 + r * 2 + 1], sT[b * 4 + 1 * 2 + c], acc);
        sY[tid] = acc;
    }
    // ---- head vectors ab(g) for this block's 4 groups (threads 32..35) ----
    if (tid >= 32 && tid < 36) {
        const int g = blockIdx.x * 4 + (tid - 32);
        const int b0 = (g >> 10) & 1;            // x_0 = MSB of g
        // v(x0)_s = U[2*x0+s, 0]
        float2 w0 = bufA[(2 * b0 + 0) * 4 + 0];
        float2 w1 = bufA[(2 * b0 + 1) * 4 + 0];
        #pragma unroll
        for (int k = 1; k <= 10; k++) {
            const int b = (g >> (10 - k)) & 1;   // x_k
            float2 n0 = cfma2(sT[b * 4 + 0], w0, cmul(sT[b * 4 + 1], w1));
            float2 n1 = cfma2(sT[b * 4 + 2], w0, cmul(sT[b * 4 + 3], w1));
            w0 = n0; w1 = n1;
        }
        sAB[(tid - 32) * 2 + 0] = w0;
        sAB[(tid - 32) * 2 + 1] = w1;
    }
    __syncthreads();

    // ---- tail row-vectors m(j) for j = 2*tid, 2*tid+1 ----
    // m(j)^T = e_{x19}^T T[x18] . Y[x17,x16] . Y[x15,x14] . Y[x13,x12] . T[x11]
    // j bits: x19=bit0, x18=bit1, ..., x11=bit8.
    // Y index is a*2+b with a = LOWER bit of the field (left matrix).
    const int j0 = 2 * tid;
    const int b18   = (j0 >> 1) & 1;
    const int i1716 = (((j0 >> 2) & 1) << 1) | ((j0 >> 3) & 1);  // x17*2 + x16
    const int i1514 = (((j0 >> 4) & 1) << 1) | ((j0 >> 5) & 1);  // x15*2 + x14
    const int i1312 = (((j0 >> 6) & 1) << 1) | ((j0 >> 7) & 1);  // x13*2 + x12
    const int b11   = (j0 >> 8) & 1;

    // init rows of T[x18]: rA -> x19=0 (row 0), rB -> x19=1 (row 1)
    float2 rA0 = sT[b18 * 4 + 0], rA1 = sT[b18 * 4 + 1];
    float2 rB0 = sT[b18 * 4 + 2], rB1 = sT[b18 * 4 + 3];

    #pragma unroll
    for (int step = 0; step < 3; step++) {
        const int yi = (step == 0) ? i1716 : (step == 1) ? i1514 : i1312;
        const float2 m00 = sY[yi * 4 + 0], m01 = sY[yi * 4 + 1];
        const float2 m10 = sY[yi * 4 + 2], m11 = sY[yi * 4 + 3];
        float2 nA0 = cfma2(rA0, m00, cmul(rA1, m10));
        float2 nA1 = cfma2(rA0, m01, cmul(rA1, m11));
        float2 nB0 = cfma2(rB0, m00, cmul(rB1, m10));
        float2 nB1 = cfma2(rB0, m01, cmul(rB1, m11));
        rA0 = nA0; rA1 = nA1; rB0 = nB0; rB1 = nB1;
    }
    {
        const float2 m00 = sT[b11 * 4 + 0], m01 = sT[b11 * 4 + 1];
        const float2 m10 = sT[b11 * 4 + 2], m11 = sT[b11 * 4 + 3];
        float2 nA0 = cfma2(rA0, m00, cmul(rA1, m10));
        float2 nA1 = cfma2(rA0, m01, cmul(rA1, m11));
        float2 nB0 = cfma2(rB0, m00, cmul(rB1, m10));
        float2 nB1 = cfma2(rB0, m01, cmul(rB1, m11));
        rA0 = nA0; rA1 = nA1; rB0 = nB0; rB1 = nB1;
    }

    // ---- epilogue: 4 groups x 2 outputs, coalesced float2 stores ----
    const long base = (long)blockIdx.x * 4 * 512 + j0;
    #pragma unroll
    for (int gl = 0; gl < 4; gl++) {
        const float2 a = sAB[gl * 2 + 0];
        const float2 b = sAB[gl * 2 + 1];
        float2 pA = cfma2(rA0, a, cmul(rA1, b));
        float2 pB = cfma2(rB0, a, cmul(rB1, b));
        float2 res;
        res.x = pA.x * pA.x + pA.y * pA.y;
        res.y = pB.x * pB.x + pB.y * pB.y;
        *(float2*)(out + base + gl * 512) = res;
    }
}

extern "C" void kernel_launch(void* const* d_in, const int* in_sizes, int n_in,
                              void* d_out, int out_size) {
    const float* params = (const float*)d_in[0];
    float* out = (float*)d_out;
    mps_kernel<<<512, 256>>>(params, out);
}